// round 4
// baseline (speedup 1.0000x reference)
#include <cuda_runtime.h>
#include <cstdint>

// Problem constants
#define BPC   4
#define NW    4
#define NP    16
#define NN    1024
#define DD    32
#define NFEAT (NN*DD)
#define FSZ   (NP*NFEAT)

// Feature buffer indices
#define IX   0
#define IY1  1
#define IY2  2
#define IY4  3
#define IY8  4
#define ITA  5
#define ITB  6
#define IF0  7
#define IF1  8
#define IF2  9
#define IA1  10
#define IA2  11
#define IA3  12
#define IA4  13
#define IA5  14
#define IA6  15
#define IA7  16
#define IA8  17
#define IB1  18
#define IB2  19
#define IB3  20
#define IB4  21
#define IB5  22
#define IB6  23
#define IB7  24
#define IB8  25
#define IS01 26
#define IS02 27
#define IS12 28
#define NBUF 29

__device__ float g_W[(size_t)NP * NN * NN];     // 64 MB
__device__ float g_feat[NBUF][FSZ];
__device__ float g_sq[NP * NN];
__device__ float g_invdeg[NP * NN];

__constant__ int c_pool_idx[7] = { IX, IF0, IF1, IF2, IS01, IS02, IS12 };

// ---- packed f32x2 helpers ---------------------------------------------------
typedef unsigned long long ull;

__device__ __forceinline__ ull pack_dup(float v) {
    ull r;
    asm("mov.b64 %0, {%1, %1};" : "=l"(r) : "f"(v));
    return r;
}
__device__ __forceinline__ ull fma2(ull a, ull b, ull c) {
    ull d;
    asm("fma.rn.f32x2 %0, %1, %2, %3;" : "=l"(d) : "l"(a), "l"(b), "l"(c));
    return d;
}
__device__ __forceinline__ void unpack2(ull v, float& lo, float& hi) {
    asm("mov.b64 {%0, %1}, %2;" : "=f"(lo), "=f"(hi) : "l"(v));
}

// ---------------------------------------------------------------------------
// X[p][n][d] = pc[b][n][d] * alphas[w][d]
// ---------------------------------------------------------------------------
__global__ void build_X_kernel(const float* __restrict__ pc,
                               const float* __restrict__ alphas) {
    int idx = blockIdx.x * blockDim.x + threadIdx.x;
    int d = idx & 31;
    int n = (idx >> 5) & 1023;
    int p = idx >> 15;
    int b = p >> 2;
    int w = p & 3;
    g_feat[IX][idx] = pc[(b * NN + n) * DD + d] * alphas[w * DD + d];
}

// ---------------------------------------------------------------------------
__global__ void sq_kernel() {
    int gr = blockIdx.x * blockDim.x + threadIdx.x;
    const float4* row = (const float4*)&g_feat[IX][(size_t)gr * DD];
    float s = 0.f;
#pragma unroll
    for (int i = 0; i < 8; i++) {
        float4 v = row[i];
        s += v.x * v.x + v.y * v.y + v.z * v.z + v.w * v.w;
    }
    g_sq[gr] = s;
}

// ---------------------------------------------------------------------------
// W[p][i][j] = K if K >= 0.5 else 0
// ---------------------------------------------------------------------------
__global__ __launch_bounds__(256) void w_kernel(const float* __restrict__ sigma_ptr) {
    __shared__ float Xis[DD][68];
    __shared__ float Xjs[DD][68];

    int p  = blockIdx.z;
    int i0 = blockIdx.y * 64;
    int j0 = blockIdx.x * 64;
    int tid = threadIdx.x;
    float sigma = sigma_ptr[0];

    const float* Xp = &g_feat[IX][(size_t)p * NFEAT];

#pragma unroll
    for (int it = 0; it < 2; it++) {
        int fi = tid + it * 256;
        int r  = fi >> 3;
        int c4 = (fi & 7) << 2;
        float4 vi = *(const float4*)(Xp + (i0 + r) * DD + c4);
        Xis[c4 + 0][r] = vi.x; Xis[c4 + 1][r] = vi.y;
        Xis[c4 + 2][r] = vi.z; Xis[c4 + 3][r] = vi.w;
        float4 vj = *(const float4*)(Xp + (j0 + r) * DD + c4);
        Xjs[c4 + 0][r] = vj.x; Xjs[c4 + 1][r] = vj.y;
        Xjs[c4 + 2][r] = vj.z; Xjs[c4 + 3][r] = vj.w;
    }
    __syncthreads();

    int ti = tid >> 4;
    int tj = tid & 15;
    float acc[4][4];
#pragma unroll
    for (int a = 0; a < 4; a++)
#pragma unroll
        for (int b = 0; b < 4; b++) acc[a][b] = 0.f;

#pragma unroll
    for (int d = 0; d < DD; d++) {
        float4 xa = *(const float4*)&Xis[d][ti * 4];
        float4 xb = *(const float4*)&Xjs[d][tj * 4];
        float ar[4] = { xa.x, xa.y, xa.z, xa.w };
        float br[4] = { xb.x, xb.y, xb.z, xb.w };
#pragma unroll
        for (int a = 0; a < 4; a++)
#pragma unroll
            for (int b = 0; b < 4; b++) acc[a][b] += ar[a] * br[b];
    }

    float sqi[4], sqj[4];
#pragma unroll
    for (int a = 0; a < 4; a++) sqi[a] = g_sq[p * NN + i0 + ti * 4 + a];
#pragma unroll
    for (int b = 0; b < 4; b++) sqj[b] = g_sq[p * NN + j0 + tj * 4 + b];

#pragma unroll
    for (int a = 0; a < 4; a++) {
        float4 wv;
        float wvals[4];
#pragma unroll
        for (int b = 0; b < 4; b++) {
            float dist = sqi[a] + sqj[b] - 2.f * acc[a][b];
            float K = expf(-dist / sigma);
            wvals[b] = (K >= 0.5f) ? K : 0.f;
        }
        wv.x = wvals[0]; wv.y = wvals[1]; wv.z = wvals[2]; wv.w = wvals[3];
        size_t off = (size_t)p * NN * NN + (size_t)(i0 + ti * 4 + a) * NN + j0 + tj * 4;
        *(float4*)(g_W + off) = wv;
    }
}

// ---------------------------------------------------------------------------
// invdeg[row] = 1 / sum_j W[row][j]
// ---------------------------------------------------------------------------
__global__ void deg_kernel() {
    int gr = blockIdx.x * 8 + (threadIdx.x >> 5);
    int lane = threadIdx.x & 31;
    const float* Wr = g_W + (size_t)gr * NN;
    float s = 0.f;
    for (int k = lane; k < NN; k += 32) s += Wr[k];
#pragma unroll
    for (int o = 16; o > 0; o >>= 1) s += __shfl_down_sync(0xffffffffu, s, o);
    if (lane == 0) g_invdeg[gr] = 1.0f / s;
}

// ---------------------------------------------------------------------------
// Apply lazy-walk operator: Out = 0.5*(In + (W @ In) * invdeg).
// Tile: 64 rows x 32 cols per CTA (128 threads), thread tile 4x4.
// W staged with CONTIGUOUS row reads (LDG.128) + scalar transposed STS
// (R1 layout — keeps DRAM streaming of W sequential).
// Feature tile pre-duplicated as (b,b) f32x2 pairs so the inner loop is
// exactly 3x LDS.128 + 8x FFMA2 per k step (no MOVs).
// ---------------------------------------------------------------------------
__global__ __launch_bounds__(128) void apply_kernel(int4 j0, int4 j1, int4 j2) {
    __shared__ float As[32][68];    // [k][row] transposed W tile (64 rows + pad)
    __shared__ ull   Bs2[32][32];   // [k][col] duplicated (b,b) pairs

    int p = blockIdx.z;
    int row0 = blockIdx.x * 64;
    int4 job = (blockIdx.y == 0) ? j0 : ((blockIdx.y == 1) ? j1 : j2);
    int tid = threadIdx.x;
    int cg = tid & 7;    // cols 4*cg .. +3
    int rg = tid >> 3;   // rows rg*4 .. +3 (0..15)

    const float* In  = &g_feat[job.x][(size_t)p * NFEAT];
    float*       Out = &g_feat[job.y][(size_t)p * NFEAT];
    const float* Wp  = g_W + (size_t)p * NN * NN + (size_t)row0 * NN;

    ull acc2[2][4];   // [row-pair][col]: pair0 = rows rg*4+{0,1}, pair1 = +{2,3}
#pragma unroll
    for (int a = 0; a < 2; a++)
#pragma unroll
        for (int b = 0; b < 4; b++) acc2[a][b] = 0ull;

    for (int k0 = 0; k0 < NN; k0 += 32) {
        // stage W tile (64 rows x 32 k), transposed into As via contiguous LDG
#pragma unroll
        for (int it = 0; it < 4; it++) {
            int fi = tid + it * 128;       // 0..511
            int r  = fi >> 3;              // 0..63
            int c4 = (fi & 7) << 2;
            float4 v = *(const float4*)(Wp + (size_t)r * NN + k0 + c4);
            As[c4 + 0][r] = v.x; As[c4 + 1][r] = v.y;
            As[c4 + 2][r] = v.z; As[c4 + 3][r] = v.w;
        }
        // stage feature tile duplicated: Bs2[k][c] = (b, b)
#pragma unroll
        for (int it = 0; it < 2; it++) {
            int fi = tid + it * 128;       // 0..255
            int r  = fi >> 3;
            int c4 = (fi & 7) << 2;
            float4 v = *(const float4*)(In + (k0 + r) * DD + c4);
            ulonglong2 d0, d1;
            d0.x = pack_dup(v.x); d0.y = pack_dup(v.y);
            d1.x = pack_dup(v.z); d1.y = pack_dup(v.w);
            *(ulonglong2*)&Bs2[r][c4 + 0] = d0;
            *(ulonglong2*)&Bs2[r][c4 + 2] = d1;
        }
        __syncthreads();

#pragma unroll
        for (int kk = 0; kk < 32; kk++) {
            ulonglong2 a = *(const ulonglong2*)&As[kk][rg * 4];       // rows (r0,r1),(r2,r3)
            ulonglong2 bl = *(const ulonglong2*)&Bs2[kk][cg * 4 + 0]; // (b0,b0),(b1,b1)
            ulonglong2 bh = *(const ulonglong2*)&Bs2[kk][cg * 4 + 2]; // (b2,b2),(b3,b3)
            acc2[0][0] = fma2(a.x, bl.x, acc2[0][0]);
            acc2[0][1] = fma2(a.x, bl.y, acc2[0][1]);
            acc2[0][2] = fma2(a.x, bh.x, acc2[0][2]);
            acc2[0][3] = fma2(a.x, bh.y, acc2[0][3]);
            acc2[1][0] = fma2(a.y, bl.x, acc2[1][0]);
            acc2[1][1] = fma2(a.y, bl.y, acc2[1][1]);
            acc2[1][2] = fma2(a.y, bh.x, acc2[1][2]);
            acc2[1][3] = fma2(a.y, bh.y, acc2[1][3]);
        }
        __syncthreads();
    }

    const float* Dif = (job.z >= 0) ? &g_feat[job.z][(size_t)p * NFEAT] : nullptr;
    float*       Abs = (job.w >= 0) ? &g_feat[job.w][(size_t)p * NFEAT] : nullptr;

#pragma unroll
    for (int pr = 0; pr < 2; pr++) {
        float s_lo[4], s_hi[4];
#pragma unroll
        for (int c = 0; c < 4; c++) unpack2(acc2[pr][c], s_lo[c], s_hi[c]);
#pragma unroll
        for (int e = 0; e < 2; e++) {
            int row = row0 + rg * 4 + pr * 2 + e;
            float idg = g_invdeg[p * NN + row];
            float4 vin = *(const float4*)(In + row * DD + cg * 4);
            float* s = e ? s_hi : s_lo;
            float4 o;
            o.x = 0.5f * fmaf(s[0], idg, vin.x);
            o.y = 0.5f * fmaf(s[1], idg, vin.y);
            o.z = 0.5f * fmaf(s[2], idg, vin.z);
            o.w = 0.5f * fmaf(s[3], idg, vin.w);
            *(float4*)(Out + row * DD + cg * 4) = o;
            if (Dif) {
                float4 dv = *(const float4*)(Dif + row * DD + cg * 4);
                float4 r;
                r.x = fabsf(dv.x - o.x); r.y = fabsf(dv.y - o.y);
                r.z = fabsf(dv.z - o.z); r.w = fabsf(dv.w - o.w);
                *(float4*)(Abs + row * DD + cg * 4) = r;
            }
        }
    }
}

// ---------------------------------------------------------------------------
__global__ void pool_kernel(float* __restrict__ out) {
    __shared__ float red[8][32];
    int blk = blockIdx.x;
    int p   = blockIdx.y;
    int col = threadIdx.x & 31;
    int grp = threadIdx.x >> 5;
    const float* src = &g_feat[c_pool_idx[blk]][(size_t)p * NFEAT];
    float s = 0.f;
    for (int i = 0; i < 128; i++)
        s += src[(grp * 128 + i) * DD + col];
    red[grp][col] = s;
    __syncthreads();
    if (grp == 0) {
        float t = 0.f;
#pragma unroll
        for (int g = 0; g < 8; g++) t += red[g][col];
        int b = p >> 2, w = p & 3;
        out[b * (NW * 224) + w * 224 + blk * 32 + col] = t * (1.0f / 1024.0f);
    }
}

// ---------------------------------------------------------------------------
extern "C" void kernel_launch(void* const* d_in, const int* in_sizes, int n_in,
                              void* d_out, int out_size) {
    const float* pc     = (const float*)d_in[0];
    const float* alphas = (const float*)d_in[1];
    const float* sigma  = (const float*)d_in[2];
    float* out = (float*)d_out;

    build_X_kernel<<<FSZ / 256, 256>>>(pc, alphas);
    sq_kernel<<<(NP * NN) / 256, 256>>>();
    w_kernel<<<dim3(16, 16, NP), 256>>>(sigma);
    deg_kernel<<<(NP * NN) / 8, 256>>>();

    int4 dummy = make_int4(IX, ITA, -1, -1);
    auto run = [&](int nblk, int4 a, int4 b, int4 c) {
        apply_kernel<<<dim3(16, nblk, NP), 128>>>(a, b, c);
    };
    #define J4(i, o, df, ab) make_int4(i, o, df, ab)

    run(1, J4(IX,  IY1, -1, -1), dummy, dummy);
    run(1, J4(IY1, IY2, IY1, IF0), dummy, dummy);
    run(2, J4(IY2, ITA, -1, -1), J4(IF0, IA1, -1, -1), dummy);
    run(2, J4(ITA, IY4, IY2, IF1), J4(IA1, IA2, -1, -1), dummy);
    run(3, J4(IY4, ITB, -1, -1), J4(IA2, IA3, -1, -1), J4(IF1, IB1, -1, -1));
    run(3, J4(ITB, ITA, -1, -1), J4(IA3, IA4, IA2, IS01), J4(IB1, IB2, -1, -1));
    run(3, J4(ITA, ITB, -1, -1), J4(IA4, IA5, -1, -1), J4(IB2, IB3, -1, -1));
    run(3, J4(ITB, IY8, IY4, IF2), J4(IA5, IA6, -1, -1), J4(IB3, IB4, -1, -1));
    run(2, J4(IA6, IA7, -1, -1), J4(IB4, IB5, -1, -1), dummy);
    run(2, J4(IA7, IA8, IA4, IS02), J4(IB5, IB6, -1, -1), dummy);
    run(1, J4(IB6, IB7, -1, -1), dummy, dummy);
    run(1, J4(IB7, IB8, IB4, IS12), dummy, dummy);

    pool_kernel<<<dim3(7, NP), 256>>>(out);
}

// round 5
// speedup vs baseline: 2.4958x; 2.4958x over previous
#include <cuda_runtime.h>
#include <cstdint>

// Problem constants
#define BPC   4
#define NW    4
#define NP    16
#define NN    1024
#define DD    32
#define NFEAT (NN*DD)
#define FSZ   (NP*NFEAT)

// Feature buffer indices
#define IX   0
#define IY1  1
#define IY2  2
#define IY4  3
#define IY8  4
#define ITA  5
#define ITB  6
#define IF0  7
#define IF1  8
#define IF2  9
#define IA1  10
#define IA2  11
#define IA3  12
#define IA4  13
#define IA5  14
#define IA6  15
#define IA7  16
#define IA8  17
#define IB1  18
#define IB2  19
#define IB3  20
#define IB4  21
#define IB5  22
#define IB6  23
#define IB7  24
#define IB8  25
#define IS01 26
#define IS02 27
#define IS12 28
#define NBUF 29

__device__ float g_W[(size_t)NP * NN * NN];     // 64 MB
__device__ float g_feat[NBUF][FSZ];
__device__ float g_sq[NP * NN];
__device__ float g_invdeg[NP * NN];

__constant__ int c_pool_idx[7] = { IX, IF0, IF1, IF2, IS01, IS02, IS12 };

// ---- packed f32x2 helpers ---------------------------------------------------
typedef unsigned long long ull;

__device__ __forceinline__ ull pack_dup(float v) {
    ull r;
    asm("mov.b64 %0, {%1, %1};" : "=l"(r) : "f"(v));
    return r;
}
__device__ __forceinline__ ull fma2(ull a, ull b, ull c) {
    ull d;
    asm("fma.rn.f32x2 %0, %1, %2, %3;" : "=l"(d) : "l"(a), "l"(b), "l"(c));
    return d;
}
__device__ __forceinline__ void unpack2(ull v, float& lo, float& hi) {
    asm("mov.b64 {%0, %1}, %2;" : "=f"(lo), "=f"(hi) : "l"(v));
}

// ---------------------------------------------------------------------------
// X[p][n][d] = pc[b][n][d] * alphas[w][d]
// ---------------------------------------------------------------------------
__global__ void build_X_kernel(const float* __restrict__ pc,
                               const float* __restrict__ alphas) {
    int idx = blockIdx.x * blockDim.x + threadIdx.x;
    int d = idx & 31;
    int n = (idx >> 5) & 1023;
    int p = idx >> 15;
    int b = p >> 2;
    int w = p & 3;
    g_feat[IX][idx] = pc[(b * NN + n) * DD + d] * alphas[w * DD + d];
}

// ---------------------------------------------------------------------------
__global__ void sq_kernel() {
    int gr = blockIdx.x * blockDim.x + threadIdx.x;
    const float4* row = (const float4*)&g_feat[IX][(size_t)gr * DD];
    float s = 0.f;
#pragma unroll
    for (int i = 0; i < 8; i++) {
        float4 v = row[i];
        s += v.x * v.x + v.y * v.y + v.z * v.z + v.w * v.w;
    }
    g_sq[gr] = s;
}

// ---------------------------------------------------------------------------
// W[p][i][j] = K if K >= 0.5 else 0
// ---------------------------------------------------------------------------
__global__ __launch_bounds__(256) void w_kernel(const float* __restrict__ sigma_ptr) {
    __shared__ float Xis[DD][68];
    __shared__ float Xjs[DD][68];

    int p  = blockIdx.z;
    int i0 = blockIdx.y * 64;
    int j0 = blockIdx.x * 64;
    int tid = threadIdx.x;
    float sigma = sigma_ptr[0];

    const float* Xp = &g_feat[IX][(size_t)p * NFEAT];

#pragma unroll
    for (int it = 0; it < 2; it++) {
        int fi = tid + it * 256;
        int r  = fi >> 3;
        int c4 = (fi & 7) << 2;
        float4 vi = *(const float4*)(Xp + (i0 + r) * DD + c4);
        Xis[c4 + 0][r] = vi.x; Xis[c4 + 1][r] = vi.y;
        Xis[c4 + 2][r] = vi.z; Xis[c4 + 3][r] = vi.w;
        float4 vj = *(const float4*)(Xp + (j0 + r) * DD + c4);
        Xjs[c4 + 0][r] = vj.x; Xjs[c4 + 1][r] = vj.y;
        Xjs[c4 + 2][r] = vj.z; Xjs[c4 + 3][r] = vj.w;
    }
    __syncthreads();

    int ti = tid >> 4;
    int tj = tid & 15;
    float acc[4][4];
#pragma unroll
    for (int a = 0; a < 4; a++)
#pragma unroll
        for (int b = 0; b < 4; b++) acc[a][b] = 0.f;

#pragma unroll
    for (int d = 0; d < DD; d++) {
        float4 xa = *(const float4*)&Xis[d][ti * 4];
        float4 xb = *(const float4*)&Xjs[d][tj * 4];
        float ar[4] = { xa.x, xa.y, xa.z, xa.w };
        float br[4] = { xb.x, xb.y, xb.z, xb.w };
#pragma unroll
        for (int a = 0; a < 4; a++)
#pragma unroll
            for (int b = 0; b < 4; b++) acc[a][b] += ar[a] * br[b];
    }

    float sqi[4], sqj[4];
#pragma unroll
    for (int a = 0; a < 4; a++) sqi[a] = g_sq[p * NN + i0 + ti * 4 + a];
#pragma unroll
    for (int b = 0; b < 4; b++) sqj[b] = g_sq[p * NN + j0 + tj * 4 + b];

#pragma unroll
    for (int a = 0; a < 4; a++) {
        float4 wv;
        float wvals[4];
#pragma unroll
        for (int b = 0; b < 4; b++) {
            float dist = sqi[a] + sqj[b] - 2.f * acc[a][b];
            float K = expf(-dist / sigma);
            wvals[b] = (K >= 0.5f) ? K : 0.f;
        }
        wv.x = wvals[0]; wv.y = wvals[1]; wv.z = wvals[2]; wv.w = wvals[3];
        size_t off = (size_t)p * NN * NN + (size_t)(i0 + ti * 4 + a) * NN + j0 + tj * 4;
        *(float4*)(g_W + off) = wv;
    }
}

// ---------------------------------------------------------------------------
// invdeg[row] = 1 / sum_j W[row][j]
// ---------------------------------------------------------------------------
__global__ void deg_kernel() {
    int gr = blockIdx.x * 8 + (threadIdx.x >> 5);
    int lane = threadIdx.x & 31;
    const float* Wr = g_W + (size_t)gr * NN;
    float s = 0.f;
    for (int k = lane; k < NN; k += 32) s += Wr[k];
#pragma unroll
    for (int o = 16; o > 0; o >>= 1) s += __shfl_down_sync(0xffffffffu, s, o);
    if (lane == 0) g_invdeg[gr] = 1.0f / s;
}

// ---------------------------------------------------------------------------
// Apply lazy-walk operator: Out = 0.5*(In + (W @ In) * invdeg).
// Tile: 64 rows x 32 cols per CTA (128 threads), thread tile 4x4.
// - W tile stored ROW-MAJOR As[64][36] (no transpose): staging is pure
//   LDG.128 -> STS.128 (floor-cost, no scalar-STS bank conflicts).
// - Register double-buffering: next chunk's W+B prefetched into registers
//   during current chunk's compute (hides DRAM/L2 latency).
// - Inner loop over k in groups of 4: per group 4x LDS.128 (A rows) +
//   4x 16B B loads + 16 dup-MOV + 32 FFMA2. Same math order as the
//   1052us kernel -> bitwise identical results.
// ---------------------------------------------------------------------------
__global__ __launch_bounds__(128) void apply_kernel(int4 j0, int4 j1, int4 j2) {
    __shared__ float As[64][36];    // [row][k], stride 36 floats (144B, 16B-aligned)
    __shared__ float Bs[32][32];    // [k][col]

    int p = blockIdx.z;
    int row0 = blockIdx.x * 64;
    int4 job = (blockIdx.y == 0) ? j0 : ((blockIdx.y == 1) ? j1 : j2);
    int tid = threadIdx.x;
    int cg = tid & 7;    // cols 4*cg .. +3
    int rg = tid >> 3;   // rows rg*4 .. +3 (0..15)

    const float* In  = &g_feat[job.x][(size_t)p * NFEAT];
    float*       Out = &g_feat[job.y][(size_t)p * NFEAT];
    const float* Wp  = g_W + (size_t)p * NN * NN + (size_t)row0 * NN;

    // staging coordinates (per thread)
    int sa_r  = tid >> 3;          // A: rows sa_r + 16*it (0..63)
    int sa_c4 = (tid & 7) << 2;    // A: k offset
    // B: fi = tid + it*128 -> r = fi>>3 (0..31), c4 = (fi&7)<<2

    ull acc2[4][2];
#pragma unroll
    for (int a = 0; a < 4; a++) { acc2[a][0] = 0ull; acc2[a][1] = 0ull; }

    // prefetch chunk 0 into registers
    float4 wreg[4], breg[2];
#pragma unroll
    for (int it = 0; it < 4; it++)
        wreg[it] = *(const float4*)(Wp + (size_t)(sa_r + 16 * it) * NN + sa_c4);
#pragma unroll
    for (int it = 0; it < 2; it++) {
        int fi = tid + it * 128;
        breg[it] = *(const float4*)(In + (fi >> 3) * DD + ((fi & 7) << 2));
    }

    for (int c = 0; c < 32; c++) {
        // store current chunk's registers to smem (STS.128, floor cost)
#pragma unroll
        for (int it = 0; it < 4; it++)
            *(float4*)&As[sa_r + 16 * it][sa_c4] = wreg[it];
#pragma unroll
        for (int it = 0; it < 2; it++) {
            int fi = tid + it * 128;
            *(float4*)&Bs[fi >> 3][(fi & 7) << 2] = breg[it];
        }
        __syncthreads();

        // prefetch next chunk (retires during compute below)
        if (c < 31) {
            int k0n = (c + 1) * 32;
#pragma unroll
            for (int it = 0; it < 4; it++)
                wreg[it] = *(const float4*)(Wp + (size_t)(sa_r + 16 * it) * NN + k0n + sa_c4);
#pragma unroll
            for (int it = 0; it < 2; it++) {
                int fi = tid + it * 128;
                breg[it] = *(const float4*)(In + (k0n + (fi >> 3)) * DD + ((fi & 7) << 2));
            }
        }

        // compute 32 k-steps, 4 at a time
#pragma unroll
        for (int k4 = 0; k4 < 32; k4 += 4) {
            float4 ar[4];
#pragma unroll
            for (int a = 0; a < 4; a++)
                ar[a] = *(const float4*)&As[rg * 4 + a][k4];
            ulonglong2 bv[4];
#pragma unroll
            for (int i = 0; i < 4; i++)
                bv[i] = *(const ulonglong2*)&Bs[k4 + i][cg * 4];
#pragma unroll
            for (int i = 0; i < 4; i++) {
#pragma unroll
                for (int a = 0; a < 4; a++) {
                    float av = ((const float*)&ar[a])[i];
                    ull ad = pack_dup(av);
                    acc2[a][0] = fma2(ad, bv[i].x, acc2[a][0]);
                    acc2[a][1] = fma2(ad, bv[i].y, acc2[a][1]);
                }
            }
        }
        __syncthreads();
    }

    const float* Dif = (job.z >= 0) ? &g_feat[job.z][(size_t)p * NFEAT] : nullptr;
    float*       Abs = (job.w >= 0) ? &g_feat[job.w][(size_t)p * NFEAT] : nullptr;

#pragma unroll
    for (int a = 0; a < 4; a++) {
        int row = row0 + rg * 4 + a;
        float idg = g_invdeg[p * NN + row];
        float4 vin = *(const float4*)(In + row * DD + cg * 4);
        float s0, s1, s2, s3;
        unpack2(acc2[a][0], s0, s1);
        unpack2(acc2[a][1], s2, s3);
        float4 o;
        o.x = 0.5f * fmaf(s0, idg, vin.x);
        o.y = 0.5f * fmaf(s1, idg, vin.y);
        o.z = 0.5f * fmaf(s2, idg, vin.z);
        o.w = 0.5f * fmaf(s3, idg, vin.w);
        *(float4*)(Out + row * DD + cg * 4) = o;
        if (Dif) {
            float4 dv = *(const float4*)(Dif + row * DD + cg * 4);
            float4 r;
            r.x = fabsf(dv.x - o.x); r.y = fabsf(dv.y - o.y);
            r.z = fabsf(dv.z - o.z); r.w = fabsf(dv.w - o.w);
            *(float4*)(Abs + row * DD + cg * 4) = r;
        }
    }
}

// ---------------------------------------------------------------------------
__global__ void pool_kernel(float* __restrict__ out) {
    __shared__ float red[8][32];
    int blk = blockIdx.x;
    int p   = blockIdx.y;
    int col = threadIdx.x & 31;
    int grp = threadIdx.x >> 5;
    const float* src = &g_feat[c_pool_idx[blk]][(size_t)p * NFEAT];
    float s = 0.f;
    for (int i = 0; i < 128; i++)
        s += src[(grp * 128 + i) * DD + col];
    red[grp][col] = s;
    __syncthreads();
    if (grp == 0) {
        float t = 0.f;
#pragma unroll
        for (int g = 0; g < 8; g++) t += red[g][col];
        int b = p >> 2, w = p & 3;
        out[b * (NW * 224) + w * 224 + blk * 32 + col] = t * (1.0f / 1024.0f);
    }
}

// ---------------------------------------------------------------------------
extern "C" void kernel_launch(void* const* d_in, const int* in_sizes, int n_in,
                              void* d_out, int out_size) {
    const float* pc     = (const float*)d_in[0];
    const float* alphas = (const float*)d_in[1];
    const float* sigma  = (const float*)d_in[2];
    float* out = (float*)d_out;

    build_X_kernel<<<FSZ / 256, 256>>>(pc, alphas);
    sq_kernel<<<(NP * NN) / 256, 256>>>();
    w_kernel<<<dim3(16, 16, NP), 256>>>(sigma);
    deg_kernel<<<(NP * NN) / 8, 256>>>();

    int4 dummy = make_int4(IX, ITA, -1, -1);
    auto run = [&](int nblk, int4 a, int4 b, int4 c) {
        apply_kernel<<<dim3(16, nblk, NP), 128>>>(a, b, c);
    };
    #define J4(i, o, df, ab) make_int4(i, o, df, ab)

    run(1, J4(IX,  IY1, -1, -1), dummy, dummy);
    run(1, J4(IY1, IY2, IY1, IF0), dummy, dummy);
    run(2, J4(IY2, ITA, -1, -1), J4(IF0, IA1, -1, -1), dummy);
    run(2, J4(ITA, IY4, IY2, IF1), J4(IA1, IA2, -1, -1), dummy);
    run(3, J4(IY4, ITB, -1, -1), J4(IA2, IA3, -1, -1), J4(IF1, IB1, -1, -1));
    run(3, J4(ITB, ITA, -1, -1), J4(IA3, IA4, IA2, IS01), J4(IB1, IB2, -1, -1));
    run(3, J4(ITA, ITB, -1, -1), J4(IA4, IA5, -1, -1), J4(IB2, IB3, -1, -1));
    run(3, J4(ITB, IY8, IY4, IF2), J4(IA5, IA6, -1, -1), J4(IB3, IB4, -1, -1));
    run(2, J4(IA6, IA7, -1, -1), J4(IB4, IB5, -1, -1), dummy);
    run(2, J4(IA7, IA8, IA4, IS02), J4(IB5, IB6, -1, -1), dummy);
    run(1, J4(IB6, IB7, -1, -1), dummy, dummy);
    run(1, J4(IB7, IB8, IB4, IS12), dummy, dummy);

    pool_kernel<<<dim3(7, NP), 256>>>(out);
}

// round 6
// speedup vs baseline: 2.8613x; 1.1464x over previous
#include <cuda_runtime.h>
#include <cstdint>

// Problem constants
#define BPC   4
#define NW    4
#define NP    16
#define NN    1024
#define DD    32
#define NFEAT (NN*DD)
#define FSZ   (NP*NFEAT)

// Feature buffer indices
#define IX   0
#define IY1  1
#define IY2  2
#define IY4  3
#define IY8  4
#define ITA  5
#define ITB  6
#define IF0  7
#define IF1  8
#define IF2  9
#define IA1  10
#define IA2  11
#define IA3  12
#define IA4  13
#define IA5  14
#define IA6  15
#define IA7  16
#define IA8  17
#define IB1  18
#define IB2  19
#define IB3  20
#define IB4  21
#define IB5  22
#define IB6  23
#define IB7  24
#define IB8  25
#define IS01 26
#define IS02 27
#define IS12 28
#define NBUF 29

__device__ float g_W[(size_t)NP * NN * NN];     // 64 MB
__device__ float g_feat[NBUF][FSZ];
__device__ float g_sq[NP * NN];
__device__ float g_invdeg[NP * NN];

__constant__ int c_pool_idx[7] = { IX, IF0, IF1, IF2, IS01, IS02, IS12 };

// ---- packed f32x2 helpers ---------------------------------------------------
typedef unsigned long long ull;

__device__ __forceinline__ ull pack_dup(float v) {
    ull r;
    asm("mov.b64 %0, {%1, %1};" : "=l"(r) : "f"(v));
    return r;
}
__device__ __forceinline__ ull fma2(ull a, ull b, ull c) {
    ull d;
    asm("fma.rn.f32x2 %0, %1, %2, %3;" : "=l"(d) : "l"(a), "l"(b), "l"(c));
    return d;
}
__device__ __forceinline__ void unpack2(ull v, float& lo, float& hi) {
    asm("mov.b64 {%0, %1}, %2;" : "=f"(lo), "=f"(hi) : "l"(v));
}

// ---------------------------------------------------------------------------
// X[p][n][d] = pc[b][n][d] * alphas[w][d]
// ---------------------------------------------------------------------------
__global__ void build_X_kernel(const float* __restrict__ pc,
                               const float* __restrict__ alphas) {
    int idx = blockIdx.x * blockDim.x + threadIdx.x;
    int d = idx & 31;
    int n = (idx >> 5) & 1023;
    int p = idx >> 15;
    int b = p >> 2;
    int w = p & 3;
    g_feat[IX][idx] = pc[(b * NN + n) * DD + d] * alphas[w * DD + d];
}

// ---------------------------------------------------------------------------
__global__ void sq_kernel() {
    int gr = blockIdx.x * blockDim.x + threadIdx.x;
    const float4* row = (const float4*)&g_feat[IX][(size_t)gr * DD];
    float s = 0.f;
#pragma unroll
    for (int i = 0; i < 8; i++) {
        float4 v = row[i];
        s += v.x * v.x + v.y * v.y + v.z * v.z + v.w * v.w;
    }
    g_sq[gr] = s;
}

// ---------------------------------------------------------------------------
// W[p][i][j] = K if K >= 0.5 else 0
// ---------------------------------------------------------------------------
__global__ __launch_bounds__(256) void w_kernel(const float* __restrict__ sigma_ptr) {
    __shared__ float Xis[DD][68];
    __shared__ float Xjs[DD][68];

    int p  = blockIdx.z;
    int i0 = blockIdx.y * 64;
    int j0 = blockIdx.x * 64;
    int tid = threadIdx.x;
    float sigma = sigma_ptr[0];

    const float* Xp = &g_feat[IX][(size_t)p * NFEAT];

#pragma unroll
    for (int it = 0; it < 2; it++) {
        int fi = tid + it * 256;
        int r  = fi >> 3;
        int c4 = (fi & 7) << 2;
        float4 vi = *(const float4*)(Xp + (i0 + r) * DD + c4);
        Xis[c4 + 0][r] = vi.x; Xis[c4 + 1][r] = vi.y;
        Xis[c4 + 2][r] = vi.z; Xis[c4 + 3][r] = vi.w;
        float4 vj = *(const float4*)(Xp + (j0 + r) * DD + c4);
        Xjs[c4 + 0][r] = vj.x; Xjs[c4 + 1][r] = vj.y;
        Xjs[c4 + 2][r] = vj.z; Xjs[c4 + 3][r] = vj.w;
    }
    __syncthreads();

    int ti = tid >> 4;
    int tj = tid & 15;
    float acc[4][4];
#pragma unroll
    for (int a = 0; a < 4; a++)
#pragma unroll
        for (int b = 0; b < 4; b++) acc[a][b] = 0.f;

#pragma unroll
    for (int d = 0; d < DD; d++) {
        float4 xa = *(const float4*)&Xis[d][ti * 4];
        float4 xb = *(const float4*)&Xjs[d][tj * 4];
        float ar[4] = { xa.x, xa.y, xa.z, xa.w };
        float br[4] = { xb.x, xb.y, xb.z, xb.w };
#pragma unroll
        for (int a = 0; a < 4; a++)
#pragma unroll
            for (int b = 0; b < 4; b++) acc[a][b] += ar[a] * br[b];
    }

    float sqi[4], sqj[4];
#pragma unroll
    for (int a = 0; a < 4; a++) sqi[a] = g_sq[p * NN + i0 + ti * 4 + a];
#pragma unroll
    for (int b = 0; b < 4; b++) sqj[b] = g_sq[p * NN + j0 + tj * 4 + b];

#pragma unroll
    for (int a = 0; a < 4; a++) {
        float4 wv;
        float wvals[4];
#pragma unroll
        for (int b = 0; b < 4; b++) {
            float dist = sqi[a] + sqj[b] - 2.f * acc[a][b];
            float K = expf(-dist / sigma);
            wvals[b] = (K >= 0.5f) ? K : 0.f;
        }
        wv.x = wvals[0]; wv.y = wvals[1]; wv.z = wvals[2]; wv.w = wvals[3];
        size_t off = (size_t)p * NN * NN + (size_t)(i0 + ti * 4 + a) * NN + j0 + tj * 4;
        *(float4*)(g_W + off) = wv;
    }
}

// ---------------------------------------------------------------------------
// invdeg[row] = 1 / sum_j W[row][j]
// ---------------------------------------------------------------------------
__global__ void deg_kernel() {
    int gr = blockIdx.x * 8 + (threadIdx.x >> 5);
    int lane = threadIdx.x & 31;
    const float* Wr = g_W + (size_t)gr * NN;
    float s = 0.f;
    for (int k = lane; k < NN; k += 32) s += Wr[k];
#pragma unroll
    for (int o = 16; o > 0; o >>= 1) s += __shfl_down_sync(0xffffffffu, s, o);
    if (lane == 0) g_invdeg[gr] = 1.0f / s;
}

// ---------------------------------------------------------------------------
// Multi-job apply: stages each W tile ONCE, applies to NJ feature blocks.
// Out_j = 0.5*(In_j + (W @ In_j) * invdeg); optional |diff - out| per job.
// Tile: 64 rows x 32 cols, 128 threads, thread tile 4x4 per job.
// Per-job FMA order identical to the single-job kernel (bitwise same result).
// ---------------------------------------------------------------------------
template <int NJ>
__global__ __launch_bounds__(128) void apply_kernel(int4 j0, int4 j1, int4 j2) {
    __shared__ float As[64][36];        // [row][k]
    __shared__ float Bs[NJ][32][32];    // [job][k][col]

    int p = blockIdx.z;
    int row0 = blockIdx.x * 64;
    int4 jobs[3] = { j0, j1, j2 };
    int tid = threadIdx.x;
    int cg = tid & 7;
    int rg = tid >> 3;

    const float* In[NJ];
    float*       Out[NJ];
#pragma unroll
    for (int j = 0; j < NJ; j++) {
        In[j]  = &g_feat[jobs[j].x][(size_t)p * NFEAT];
        Out[j] = &g_feat[jobs[j].y][(size_t)p * NFEAT];
    }
    const float* Wp = g_W + (size_t)p * NN * NN + (size_t)row0 * NN;

    int sa_r  = tid >> 3;
    int sa_c4 = (tid & 7) << 2;

    ull acc2[NJ][4][2];
#pragma unroll
    for (int j = 0; j < NJ; j++)
#pragma unroll
        for (int a = 0; a < 4; a++) { acc2[j][a][0] = 0ull; acc2[j][a][1] = 0ull; }

    // prefetch chunk 0
    float4 wreg[4], breg[NJ][2];
#pragma unroll
    for (int it = 0; it < 4; it++)
        wreg[it] = *(const float4*)(Wp + (size_t)(sa_r + 16 * it) * NN + sa_c4);
#pragma unroll
    for (int j = 0; j < NJ; j++)
#pragma unroll
        for (int it = 0; it < 2; it++) {
            int fi = tid + it * 128;
            breg[j][it] = *(const float4*)(In[j] + (fi >> 3) * DD + ((fi & 7) << 2));
        }

    for (int c = 0; c < 32; c++) {
#pragma unroll
        for (int it = 0; it < 4; it++)
            *(float4*)&As[sa_r + 16 * it][sa_c4] = wreg[it];
#pragma unroll
        for (int j = 0; j < NJ; j++)
#pragma unroll
            for (int it = 0; it < 2; it++) {
                int fi = tid + it * 128;
                *(float4*)&Bs[j][fi >> 3][(fi & 7) << 2] = breg[j][it];
            }
        __syncthreads();

        if (c < 31) {
            int k0n = (c + 1) * 32;
#pragma unroll
            for (int it = 0; it < 4; it++)
                wreg[it] = *(const float4*)(Wp + (size_t)(sa_r + 16 * it) * NN + k0n + sa_c4);
#pragma unroll
            for (int j = 0; j < NJ; j++)
#pragma unroll
                for (int it = 0; it < 2; it++) {
                    int fi = tid + it * 128;
                    breg[j][it] = *(const float4*)(In[j] + (k0n + (fi >> 3)) * DD + ((fi & 7) << 2));
                }
        }

#pragma unroll
        for (int k4 = 0; k4 < 32; k4 += 4) {
            float4 ar[4];
#pragma unroll
            for (int a = 0; a < 4; a++)
                ar[a] = *(const float4*)&As[rg * 4 + a][k4];
#pragma unroll
            for (int j = 0; j < NJ; j++) {
                ulonglong2 bv[4];
#pragma unroll
                for (int i = 0; i < 4; i++)
                    bv[i] = *(const ulonglong2*)&Bs[j][k4 + i][cg * 4];
#pragma unroll
                for (int i = 0; i < 4; i++) {
#pragma unroll
                    for (int a = 0; a < 4; a++) {
                        float av = ((const float*)&ar[a])[i];
                        ull ad = pack_dup(av);
                        acc2[j][a][0] = fma2(ad, bv[i].x, acc2[j][a][0]);
                        acc2[j][a][1] = fma2(ad, bv[i].y, acc2[j][a][1]);
                    }
                }
            }
        }
        __syncthreads();
    }

#pragma unroll
    for (int j = 0; j < NJ; j++) {
        const float* Dif = (jobs[j].z >= 0) ? &g_feat[jobs[j].z][(size_t)p * NFEAT] : nullptr;
        float*       Abs = (jobs[j].w >= 0) ? &g_feat[jobs[j].w][(size_t)p * NFEAT] : nullptr;
#pragma unroll
        for (int a = 0; a < 4; a++) {
            int row = row0 + rg * 4 + a;
            float idg = g_invdeg[p * NN + row];
            float4 vin = *(const float4*)(In[j] + row * DD + cg * 4);
            float s0, s1, s2, s3;
            unpack2(acc2[j][a][0], s0, s1);
            unpack2(acc2[j][a][1], s2, s3);
            float4 o;
            o.x = 0.5f * fmaf(s0, idg, vin.x);
            o.y = 0.5f * fmaf(s1, idg, vin.y);
            o.z = 0.5f * fmaf(s2, idg, vin.z);
            o.w = 0.5f * fmaf(s3, idg, vin.w);
            *(float4*)(Out[j] + row * DD + cg * 4) = o;
            if (Dif) {
                float4 dv = *(const float4*)(Dif + row * DD + cg * 4);
                float4 r;
                r.x = fabsf(dv.x - o.x); r.y = fabsf(dv.y - o.y);
                r.z = fabsf(dv.z - o.z); r.w = fabsf(dv.w - o.w);
                *(float4*)(Abs + row * DD + cg * 4) = r;
            }
        }
    }
}

// ---------------------------------------------------------------------------
__global__ void pool_kernel(float* __restrict__ out) {
    __shared__ float red[8][32];
    int blk = blockIdx.x;
    int p   = blockIdx.y;
    int col = threadIdx.x & 31;
    int grp = threadIdx.x >> 5;
    const float* src = &g_feat[c_pool_idx[blk]][(size_t)p * NFEAT];
    float s = 0.f;
    for (int i = 0; i < 128; i++)
        s += src[(grp * 128 + i) * DD + col];
    red[grp][col] = s;
    __syncthreads();
    if (grp == 0) {
        float t = 0.f;
#pragma unroll
        for (int g = 0; g < 8; g++) t += red[g][col];
        int b = p >> 2, w = p & 3;
        out[b * (NW * 224) + w * 224 + blk * 32 + col] = t * (1.0f / 1024.0f);
    }
}

// ---------------------------------------------------------------------------
extern "C" void kernel_launch(void* const* d_in, const int* in_sizes, int n_in,
                              void* d_out, int out_size) {
    const float* pc     = (const float*)d_in[0];
    const float* alphas = (const float*)d_in[1];
    const float* sigma  = (const float*)d_in[2];
    float* out = (float*)d_out;

    build_X_kernel<<<FSZ / 256, 256>>>(pc, alphas);
    sq_kernel<<<(NP * NN) / 256, 256>>>();
    w_kernel<<<dim3(16, 16, NP), 256>>>(sigma);
    deg_kernel<<<(NP * NN) / 8, 256>>>();

    int4 dummy = make_int4(IX, ITA, -1, -1);
    dim3 grid(16, 1, NP);
    auto run1 = [&](int4 a) { apply_kernel<1><<<grid, 128>>>(a, dummy, dummy); };
    auto run2 = [&](int4 a, int4 b) { apply_kernel<2><<<grid, 128>>>(a, b, dummy); };
    auto run3 = [&](int4 a, int4 b, int4 c) { apply_kernel<3><<<grid, 128>>>(a, b, c); };
    #define J4(i, o, df, ab) make_int4(i, o, df, ab)

    run1(J4(IX,  IY1, -1, -1));
    run1(J4(IY1, IY2, IY1, IF0));
    run2(J4(IY2, ITA, -1, -1), J4(IF0, IA1, -1, -1));
    run2(J4(ITA, IY4, IY2, IF1), J4(IA1, IA2, -1, -1));
    run3(J4(IY4, ITB, -1, -1), J4(IA2, IA3, -1, -1), J4(IF1, IB1, -1, -1));
    run3(J4(ITB, ITA, -1, -1), J4(IA3, IA4, IA2, IS01), J4(IB1, IB2, -1, -1));
    run3(J4(ITA, ITB, -1, -1), J4(IA4, IA5, -1, -1), J4(IB2, IB3, -1, -1));
    run3(J4(ITB, IY8, IY4, IF2), J4(IA5, IA6, -1, -1), J4(IB3, IB4, -1, -1));
    run2(J4(IA6, IA7, -1, -1), J4(IB4, IB5, -1, -1));
    run2(J4(IA7, IA8, IA4, IS02), J4(IB5, IB6, -1, -1));
    run1(J4(IB6, IB7, -1, -1));
    run1(J4(IB7, IB8, IB4, IS12));

    pool_kernel<<<dim3(7, NP), 256>>>(out);
}